// round 4
// baseline (speedup 1.0000x reference)
#include <cuda_runtime.h>
#include <cstdint>

// ---------------- problem constants ----------------
#define NFRM   128
#define HW     50176            // 224*224
#define GDIM   48
#define VVOX   (GDIM*GDIM*GDIM) // 110592
#define VW     (VVOX/32)        // 3456 words
#define KSEL   16
#define RANKLO 25087            // floor(0.5*(HW-1))
#define THR    0.1f
#define NT     256

// ---------------- device scratch (no allocations allowed) ----------------
__device__ float    g_fmn[NFRM][3];
__device__ float    g_fmx[NFRM][3];
__device__ unsigned g_occ[NFRM][VW];      // 1.77 MB
__device__ int      g_gains[KSEL][NFRM];  // per-iteration gains (no WAR hazard)
__device__ unsigned g_barcnt;             // monotone grid-barrier ticket counter

// ---------------- grid barrier (128 co-resident blocks, ticket-based) ----------------
__device__ __forceinline__ void grid_sync() {
    __syncthreads();
    if (threadIdx.x == 0) {
        __threadfence();
        unsigned ticket = atomicAdd(&g_barcnt, 1u);
        unsigned target = (ticket / NFRM + 1u) * NFRM;
        volatile unsigned* p = &g_barcnt;
        while (*p < target) { }
        __threadfence();
    }
    __syncthreads();
}

// ---------------- the single fused kernel ----------------
__global__ void __launch_bounds__(NT, 1)
k_fused(const float* __restrict__ wp, const float* __restrict__ conf,
        float* __restrict__ out, int out_size)
{
    // s_mem layout: phase A: hist[4096] (spans into covered region, fine)
    //               phase B+greedy: [0..VW) = own frame's occ bitmap, [VW..2VW) = covered copy
    __shared__ unsigned s_mem[2 * VW];            // 27648 B
    __shared__ unsigned s_b[4];                   // binA, binB, rA', rB'
    __shared__ unsigned s_u[2];                   // diverged-case umax/umin
    __shared__ float    s_pm[4];                  // pmin0..2, voxel size
    __shared__ float    s_rf[6][NT / 32];         // min/max block reduce
    __shared__ int      s_redi[NT / 32];          // int block reduce
    __shared__ int      s_g[NFRM];                // gains snapshot
    __shared__ int      s_best;

    const int tid = threadIdx.x;
    const int f   = blockIdx.x;
    const float* c   = conf + (size_t)f * HW;
    const float* wpf = wp   + (size_t)f * HW * 3;

    // ================= Phase A1: joint 2-rank radix select (percentile) =================
    unsigned prefix = 0u, pmask = 0u;
    int rA = RANKLO, rB = RANKLO + 1;
    int diverged = 0;
    unsigned maskA = 0u, maskB = 0u, prefA = 0u, prefB = 0u;
    const int shifts[3] = {20, 8, 0};
    const int bitsc[3]  = {12, 12, 8};

    for (int p = 0; p < 3 && !diverged; p++) {
        const int shift = shifts[p];
        const int nb = 1 << bitsc[p];
        const unsigned fm = (unsigned)(nb - 1);
        for (int b = tid; b < nb; b += NT) s_mem[b] = 0u;
        __syncthreads();
        for (int j = tid; j < HW; j += NT) {
            unsigned u = __float_as_uint(c[j]);
            if ((u & pmask) == prefix) atomicAdd(&s_mem[(u >> shift) & fm], 1u);
        }
        __syncthreads();
        if (tid == 0) {
            int binA = -1, binB = -1;
            unsigned nrA = 0u, nrB = 0u, cum = 0u;
            for (int b = 0; b < nb; b++) {
                unsigned h = s_mem[b];
                if (binA < 0 && cum + h > (unsigned)rA) { binA = b; nrA = (unsigned)rA - cum; }
                if (binB < 0 && cum + h > (unsigned)rB) { binB = b; nrB = (unsigned)rB - cum; }
                cum += h;
                if (binB >= 0) break;
            }
            s_b[0] = (unsigned)binA; s_b[1] = (unsigned)binB; s_b[2] = nrA; s_b[3] = nrB;
        }
        __syncthreads();
        unsigned binA = s_b[0], binB = s_b[1];
        if (binA == binB) {
            prefix |= binA << shift;
            pmask  |= fm << shift;
            rA = (int)s_b[2];
            rB = (int)s_b[3];
        } else {
            // rank boundary falls between bins: valA = max in prefA, valB = min in prefB
            maskA = pmask | (fm << shift);
            maskB = maskA;
            prefA = prefix | (binA << shift);
            prefB = prefix | (binB << shift);
            diverged = 1;
        }
        __syncthreads();
    }

    float vA, vB;
    if (!diverged) {
        vA = vB = __uint_as_float(prefix);   // full 32-bit value after all 3 passes
    } else {
        unsigned umax = 0u, umin = 0xFFFFFFFFu;
        for (int j = tid; j < HW; j += NT) {
            unsigned u = __float_as_uint(c[j]);
            if ((u & maskA) == prefA) umax = max(umax, u);
            if ((u & maskB) == prefB) umin = min(umin, u);
        }
        #pragma unroll
        for (int o = 16; o; o >>= 1) {
            umax = max(umax, __shfl_down_sync(0xFFFFFFFFu, umax, o));
            umin = min(umin, __shfl_down_sync(0xFFFFFFFFu, umin, o));
        }
        if ((tid & 31) == 0) { s_mem[tid >> 5] = umax; s_mem[16 + (tid >> 5)] = umin; }
        __syncthreads();
        if (tid == 0) {
            unsigned a = 0u, b = 0xFFFFFFFFu;
            for (int w = 0; w < NT / 32; w++) { a = max(a, s_mem[w]); b = min(b, s_mem[16 + w]); }
            s_u[0] = a; s_u[1] = b;
        }
        __syncthreads();
        vA = __uint_as_float(s_u[0]);
        vB = __uint_as_float(s_u[1]);
    }
    const float pct = 0.5f * vA + 0.5f * vB;   // jnp.quantile frac=0.5 blend (matched R2 exactly)

    // ================= Phase A2: per-frame min/max of valid points =================
    float mn0 = 1e30f, mn1 = 1e30f, mn2 = 1e30f;
    float mx0 = -1e30f, mx1 = -1e30f, mx2 = -1e30f;
    for (int j = tid; j < HW; j += NT) {
        float cv = c[j];
        if (cv > THR && cv >= pct) {
            float x = wpf[3 * j], y = wpf[3 * j + 1], z = wpf[3 * j + 2];
            mn0 = fminf(mn0, x); mx0 = fmaxf(mx0, x);
            mn1 = fminf(mn1, y); mx1 = fmaxf(mx1, y);
            mn2 = fminf(mn2, z); mx2 = fmaxf(mx2, z);
        }
    }
    #pragma unroll
    for (int o = 16; o; o >>= 1) {
        mn0 = fminf(mn0, __shfl_down_sync(0xFFFFFFFFu, mn0, o));
        mn1 = fminf(mn1, __shfl_down_sync(0xFFFFFFFFu, mn1, o));
        mn2 = fminf(mn2, __shfl_down_sync(0xFFFFFFFFu, mn2, o));
        mx0 = fmaxf(mx0, __shfl_down_sync(0xFFFFFFFFu, mx0, o));
        mx1 = fmaxf(mx1, __shfl_down_sync(0xFFFFFFFFu, mx1, o));
        mx2 = fmaxf(mx2, __shfl_down_sync(0xFFFFFFFFu, mx2, o));
    }
    {
        int wid = tid >> 5;
        if ((tid & 31) == 0) {
            s_rf[0][wid] = mn0; s_rf[1][wid] = mn1; s_rf[2][wid] = mn2;
            s_rf[3][wid] = mx0; s_rf[4][wid] = mx1; s_rf[5][wid] = mx2;
        }
    }
    __syncthreads();
    if (tid == 0) {
        float a0 = 1e30f, a1 = 1e30f, a2 = 1e30f, b0 = -1e30f, b1 = -1e30f, b2 = -1e30f;
        for (int w = 0; w < NT / 32; w++) {
            a0 = fminf(a0, s_rf[0][w]); a1 = fminf(a1, s_rf[1][w]); a2 = fminf(a2, s_rf[2][w]);
            b0 = fmaxf(b0, s_rf[3][w]); b1 = fmaxf(b1, s_rf[4][w]); b2 = fmaxf(b2, s_rf[5][w]);
        }
        g_fmn[f][0] = a0; g_fmn[f][1] = a1; g_fmn[f][2] = a2;
        g_fmx[f][0] = b0; g_fmx[f][1] = b1; g_fmx[f][2] = b2;
    }

    grid_sync();   // all per-frame min/max published

    // global reduce + voxel size (each block computes identical values)
    if (tid == 0) {
        float pm0 = 1e30f, pm1 = 1e30f, pm2 = 1e30f;
        float px0 = -1e30f, px1 = -1e30f, px2 = -1e30f;
        for (int s = 0; s < NFRM; s++) {
            pm0 = fminf(pm0, g_fmn[s][0]); pm1 = fminf(pm1, g_fmn[s][1]); pm2 = fminf(pm2, g_fmn[s][2]);
            px0 = fmaxf(px0, g_fmx[s][0]); px1 = fmaxf(px1, g_fmx[s][1]); px2 = fmaxf(px2, g_fmx[s][2]);
        }
        float e = fminf(fminf(px0 - pm0, px1 - pm1), px2 - pm2);
        s_pm[0] = pm0; s_pm[1] = pm1; s_pm[2] = pm2;
        s_pm[3] = __fdiv_rn(e, 20.0f);
    }
    __syncthreads();
    const float p0 = s_pm[0], p1 = s_pm[1], p2 = s_pm[2], vs = s_pm[3];

    // ================= Phase B: occupancy bitmap in shared memory =================
    unsigned* bm  = s_mem;        // [0..VW)
    unsigned* cov = s_mem + VW;   // [VW..2VW)
    for (int w = tid; w < VW; w += NT) bm[w] = 0u;
    __syncthreads();
    for (int j = tid; j < HW; j += NT) {
        float cv = c[j];
        if (cv > THR && cv >= pct) {
            int ix = (int)floorf(__fdiv_rn(wpf[3 * j]     - p0, vs));
            int iy = (int)floorf(__fdiv_rn(wpf[3 * j + 1] - p1, vs));
            int iz = (int)floorf(__fdiv_rn(wpf[3 * j + 2] - p2, vs));
            ix = min(max(ix, 0), GDIM - 1);
            iy = min(max(iy, 0), GDIM - 1);
            iz = min(max(iz, 0), GDIM - 1);
            int vid = (ix * GDIM + iy) * GDIM + iz;
            atomicOr(&bm[vid >> 5], 1u << (vid & 31));
        }
    }
    __syncthreads();
    for (int w = tid; w < VW; w += NT) {
        g_occ[f][w] = bm[w];      // publish for covered updates
        cov[w] = 0u;              // init local covered copy
    }

    grid_sync();   // all occ rows published

    // ================= Greedy max-coverage: 16 iters, 1 barrier each =================
    unsigned selbits[4] = {0u, 0u, 0u, 0u};   // maintained identically by thread 0 of every block

    for (int it = 0; it < KSEL; it++) {
        // gain for own frame: pure smem compute
        int acc = 0;
        for (int w = tid; w < VW; w += NT) acc += __popc(bm[w] & ~cov[w]);
        #pragma unroll
        for (int o = 16; o; o >>= 1) acc += __shfl_down_sync(0xFFFFFFFFu, acc, o);
        if ((tid & 31) == 0) s_redi[tid >> 5] = acc;
        __syncthreads();
        if (tid == 0) {
            int tot = 0;
            for (int w = 0; w < NT / 32; w++) tot += s_redi[w];
            g_gains[it][f] = tot;
        }
        grid_sync();   // all gains for iteration `it` published

        // every block: identical argmax (first-max == jnp.argmax tie-break)
        if (tid < NFRM) s_g[tid] = g_gains[it][tid];
        __syncthreads();
        if (tid == 0) {
            int bg = -2, bs = 0;
            for (int s = 0; s < NFRM; s++) {
                int g = (selbits[s >> 5] >> (s & 31)) & 1 ? -1 : s_g[s];
                if (g > bg) { bg = g; bs = s; }
            }
            selbits[bs >> 5] |= 1u << (bs & 31);
            s_best = bs;
            if (f == 0) {                       // record outputs
                out[it] = (float)bs;
                out[KSEL + it] = (float)bg;
            }
        }
        __syncthreads();
        const unsigned* row = g_occ[s_best];
        // each thread updates exactly the cov[] words it reads in the gain loop -> no sync needed
        for (int w = tid; w < VW; w += NT) cov[w] |= row[w];
        __syncthreads();
    }

    // ================= finalize: total coverage =================
    if (f == 0) {
        int acc = 0;
        for (int w = tid; w < VW; w += NT) acc += __popc(cov[w]);
        #pragma unroll
        for (int o = 16; o; o >>= 1) acc += __shfl_down_sync(0xFFFFFFFFu, acc, o);
        if ((tid & 31) == 0) s_redi[tid >> 5] = acc;
        __syncthreads();
        if (tid == 0) {
            int tot = 0;
            for (int w = 0; w < NT / 32; w++) tot += s_redi[w];
            if (2 * KSEL < out_size) out[2 * KSEL] = (float)tot;
        }
        // defensive: zero any tail beyond 33 elements (output is poisoned to 0xAA)
        for (int w = 2 * KSEL + 1 + tid; w < out_size; w += NT) out[w] = 0.0f;
    }
}

// ---------------- launch: ONE graph node ----------------
extern "C" void kernel_launch(void* const* d_in, const int* in_sizes, int n_in,
                              void* d_out, int out_size) {
    // metadata order: depth, depth_conf, world_points, world_points_conf, pose_enc
    const float* wp   = (const float*)d_in[2];
    const float* conf = (const float*)d_in[3];
    float* out = (float*)d_out;
    k_fused<<<NFRM, NT>>>(wp, conf, out, out_size);
}

// round 5
// speedup vs baseline: 1.3421x; 1.3421x over previous
#include <cuda_runtime.h>
#include <cstdint>

// ---------------- problem constants ----------------
#define NFRM   128
#define HW     50176            // 224*224
#define GDIM   48
#define VVOX   (GDIM*GDIM*GDIM) // 110592
#define VW     (VVOX/32)        // 3456 words
#define KSEL   16
#define RANKLO 25087            // floor(0.5*(HW-1))
#define THR    0.1f
#define NT     1024
#define NW     (NT/32)

// ---------------- device scratch (no allocations allowed) ----------------
__device__ float    g_fmn[NFRM][3];
__device__ float    g_fmx[NFRM][3];
__device__ unsigned g_occ[NFRM][VW];      // 1.77 MB
__device__ int      g_gains[KSEL][NFRM];  // per-iteration gains (no WAR hazard)
__device__ unsigned g_barcnt;             // monotone grid-barrier ticket counter

// ---------------- grid barrier (128 co-resident blocks, ticket-based) ----------------
__device__ __forceinline__ void grid_sync() {
    __syncthreads();
    if (threadIdx.x == 0) {
        __threadfence();
        unsigned ticket = atomicAdd(&g_barcnt, 1u);
        unsigned target = (ticket / NFRM + 1u) * NFRM;
        volatile unsigned* p = &g_barcnt;
        while (*p < target) { }
        __threadfence();
    }
    __syncthreads();
}

// ---------------- the single fused kernel ----------------
__global__ void __launch_bounds__(NT, 1)
k_fused(const float* __restrict__ wp, const float* __restrict__ conf,
        float* __restrict__ out, int out_size)
{
    // s_mem layout: phase A: hist[4096]
    //               phase B+greedy: [0..VW) = own frame's occ bitmap, [VW..2VW) = covered copy
    __shared__ unsigned s_mem[2 * VW];            // 27648 B
    __shared__ unsigned s_b[4];                   // binA, binB, rA', rB'
    __shared__ unsigned s_u[2];                   // diverged-case umax/umin
    __shared__ float    s_pm[4];                  // pmin0..2, voxel size
    __shared__ float    s_rf[6][NW];              // min/max block reduce
    __shared__ int      s_redi[NW];               // int block reduce
    __shared__ int      s_g[NFRM];                // gains snapshot
    __shared__ int      s_best;

    const int tid = threadIdx.x;
    const int f   = blockIdx.x;
    const float*  c   = conf + (size_t)f * HW;
    const float4* c4  = (const float4*)c;
    const float*  wpf = wp   + (size_t)f * HW * 3;

    // ================= Phase A1: joint 2-rank radix select (percentile) =================
    unsigned prefix = 0u, pmask = 0u;
    int rA = RANKLO, rB = RANKLO + 1;
    int diverged = 0;
    unsigned maskA = 0u, prefA = 0u, prefB = 0u;
    const int shifts[3] = {20, 8, 0};
    const int bitsc[3]  = {12, 12, 8};

    for (int p = 0; p < 3 && !diverged; p++) {
        const int shift = shifts[p];
        const int nb = 1 << bitsc[p];
        const unsigned fm = (unsigned)(nb - 1);
        for (int b = tid; b < nb; b += NT) s_mem[b] = 0u;
        __syncthreads();
        for (int j = tid; j < HW / 4; j += NT) {
            float4 v = c4[j];
            unsigned u0 = __float_as_uint(v.x), u1 = __float_as_uint(v.y);
            unsigned u2 = __float_as_uint(v.z), u3 = __float_as_uint(v.w);
            if ((u0 & pmask) == prefix) atomicAdd(&s_mem[(u0 >> shift) & fm], 1u);
            if ((u1 & pmask) == prefix) atomicAdd(&s_mem[(u1 >> shift) & fm], 1u);
            if ((u2 & pmask) == prefix) atomicAdd(&s_mem[(u2 >> shift) & fm], 1u);
            if ((u3 & pmask) == prefix) atomicAdd(&s_mem[(u3 >> shift) & fm], 1u);
        }
        __syncthreads();
        if (tid == 0) {
            int binA = -1, binB = -1;
            unsigned nrA = 0u, nrB = 0u, cum = 0u;
            for (int b = 0; b < nb; b++) {
                unsigned h = s_mem[b];
                if (binA < 0 && cum + h > (unsigned)rA) { binA = b; nrA = (unsigned)rA - cum; }
                if (binB < 0 && cum + h > (unsigned)rB) { binB = b; nrB = (unsigned)rB - cum; }
                cum += h;
                if (binB >= 0) break;
            }
            s_b[0] = (unsigned)binA; s_b[1] = (unsigned)binB; s_b[2] = nrA; s_b[3] = nrB;
        }
        __syncthreads();
        unsigned binA = s_b[0], binB = s_b[1];
        if (binA == binB) {
            prefix |= binA << shift;
            pmask  |= fm << shift;
            rA = (int)s_b[2];
            rB = (int)s_b[3];
        } else {
            // rank boundary falls between bins: valA = max in prefA, valB = min in prefB
            maskA = pmask | (fm << shift);
            prefA = prefix | (binA << shift);
            prefB = prefix | (binB << shift);
            diverged = 1;
        }
        __syncthreads();
    }

    float vA, vB;
    if (!diverged) {
        vA = vB = __uint_as_float(prefix);   // full 32-bit value after all 3 passes
    } else {
        unsigned umax = 0u, umin = 0xFFFFFFFFu;
        for (int j = tid; j < HW / 4; j += NT) {
            float4 v = c4[j];
            unsigned uu[4] = { __float_as_uint(v.x), __float_as_uint(v.y),
                               __float_as_uint(v.z), __float_as_uint(v.w) };
            #pragma unroll
            for (int q = 0; q < 4; q++) {
                if ((uu[q] & maskA) == prefA) umax = max(umax, uu[q]);
                if ((uu[q] & maskA) == prefB) umin = min(umin, uu[q]);
            }
        }
        #pragma unroll
        for (int o = 16; o; o >>= 1) {
            umax = max(umax, __shfl_down_sync(0xFFFFFFFFu, umax, o));
            umin = min(umin, __shfl_down_sync(0xFFFFFFFFu, umin, o));
        }
        if ((tid & 31) == 0) { s_mem[tid >> 5] = umax; s_mem[NW + (tid >> 5)] = umin; }
        __syncthreads();
        if (tid == 0) {
            unsigned a = 0u, b = 0xFFFFFFFFu;
            for (int w = 0; w < NW; w++) { a = max(a, s_mem[w]); b = min(b, s_mem[NW + w]); }
            s_u[0] = a; s_u[1] = b;
        }
        __syncthreads();
        vA = __uint_as_float(s_u[0]);
        vB = __uint_as_float(s_u[1]);
    }
    const float pct = 0.5f * vA + 0.5f * vB;   // jnp.quantile frac=0.5 blend

    // ================= Phase A2: per-frame min/max of valid points =================
    float mn0 = 1e30f, mn1 = 1e30f, mn2 = 1e30f;
    float mx0 = -1e30f, mx1 = -1e30f, mx2 = -1e30f;
    for (int j = tid; j < HW; j += NT) {
        float cv = c[j];
        if (cv > THR && cv >= pct) {
            float x = wpf[3 * j], y = wpf[3 * j + 1], z = wpf[3 * j + 2];
            mn0 = fminf(mn0, x); mx0 = fmaxf(mx0, x);
            mn1 = fminf(mn1, y); mx1 = fmaxf(mx1, y);
            mn2 = fminf(mn2, z); mx2 = fmaxf(mx2, z);
        }
    }
    #pragma unroll
    for (int o = 16; o; o >>= 1) {
        mn0 = fminf(mn0, __shfl_down_sync(0xFFFFFFFFu, mn0, o));
        mn1 = fminf(mn1, __shfl_down_sync(0xFFFFFFFFu, mn1, o));
        mn2 = fminf(mn2, __shfl_down_sync(0xFFFFFFFFu, mn2, o));
        mx0 = fmaxf(mx0, __shfl_down_sync(0xFFFFFFFFu, mx0, o));
        mx1 = fmaxf(mx1, __shfl_down_sync(0xFFFFFFFFu, mx1, o));
        mx2 = fmaxf(mx2, __shfl_down_sync(0xFFFFFFFFu, mx2, o));
    }
    {
        int wid = tid >> 5;
        if ((tid & 31) == 0) {
            s_rf[0][wid] = mn0; s_rf[1][wid] = mn1; s_rf[2][wid] = mn2;
            s_rf[3][wid] = mx0; s_rf[4][wid] = mx1; s_rf[5][wid] = mx2;
        }
    }
    __syncthreads();
    if (tid == 0) {
        float a0 = 1e30f, a1 = 1e30f, a2 = 1e30f, b0 = -1e30f, b1 = -1e30f, b2 = -1e30f;
        for (int w = 0; w < NW; w++) {
            a0 = fminf(a0, s_rf[0][w]); a1 = fminf(a1, s_rf[1][w]); a2 = fminf(a2, s_rf[2][w]);
            b0 = fmaxf(b0, s_rf[3][w]); b1 = fmaxf(b1, s_rf[4][w]); b2 = fmaxf(b2, s_rf[5][w]);
        }
        g_fmn[f][0] = a0; g_fmn[f][1] = a1; g_fmn[f][2] = a2;
        g_fmx[f][0] = b0; g_fmx[f][1] = b1; g_fmx[f][2] = b2;
    }

    grid_sync();   // all per-frame min/max published

    // global reduce + voxel size (each block computes identical values)
    if (tid == 0) {
        float pm0 = 1e30f, pm1 = 1e30f, pm2 = 1e30f;
        float px0 = -1e30f, px1 = -1e30f, px2 = -1e30f;
        for (int s = 0; s < NFRM; s++) {
            pm0 = fminf(pm0, g_fmn[s][0]); pm1 = fminf(pm1, g_fmn[s][1]); pm2 = fminf(pm2, g_fmn[s][2]);
            px0 = fmaxf(px0, g_fmx[s][0]); px1 = fmaxf(px1, g_fmx[s][1]); px2 = fmaxf(px2, g_fmx[s][2]);
        }
        float e = fminf(fminf(px0 - pm0, px1 - pm1), px2 - pm2);
        s_pm[0] = pm0; s_pm[1] = pm1; s_pm[2] = pm2;
        s_pm[3] = __fdiv_rn(e, 20.0f);
    }
    __syncthreads();
    const float p0 = s_pm[0], p1 = s_pm[1], p2 = s_pm[2], vs = s_pm[3];

    // ================= Phase B: occupancy bitmap in shared memory =================
    unsigned* bm  = s_mem;        // [0..VW)
    unsigned* cov = s_mem + VW;   // [VW..2VW)
    for (int w = tid; w < VW; w += NT) bm[w] = 0u;
    __syncthreads();
    for (int j = tid; j < HW; j += NT) {
        float cv = c[j];
        if (cv > THR && cv >= pct) {
            int ix = (int)floorf(__fdiv_rn(wpf[3 * j]     - p0, vs));
            int iy = (int)floorf(__fdiv_rn(wpf[3 * j + 1] - p1, vs));
            int iz = (int)floorf(__fdiv_rn(wpf[3 * j + 2] - p2, vs));
            ix = min(max(ix, 0), GDIM - 1);
            iy = min(max(iy, 0), GDIM - 1);
            iz = min(max(iz, 0), GDIM - 1);
            int vid = (ix * GDIM + iy) * GDIM + iz;
            atomicOr(&bm[vid >> 5], 1u << (vid & 31));
        }
    }
    __syncthreads();
    for (int w = tid; w < VW; w += NT) {
        g_occ[f][w] = bm[w];      // publish for covered updates
        cov[w] = 0u;              // init local covered copy
    }

    grid_sync();   // all occ rows published

    // ================= Greedy max-coverage: 16 iters, 1 barrier each =================
    unsigned selbits[4] = {0u, 0u, 0u, 0u};   // maintained identically by thread 0 of every block

    for (int it = 0; it < KSEL; it++) {
        // gain for own frame: pure smem compute
        int acc = 0;
        for (int w = tid; w < VW; w += NT) acc += __popc(bm[w] & ~cov[w]);
        #pragma unroll
        for (int o = 16; o; o >>= 1) acc += __shfl_down_sync(0xFFFFFFFFu, acc, o);
        if ((tid & 31) == 0) s_redi[tid >> 5] = acc;
        __syncthreads();
        if (tid == 0) {
            int tot = 0;
            for (int w = 0; w < NW; w++) tot += s_redi[w];
            g_gains[it][f] = tot;
        }
        grid_sync();   // all gains for iteration `it` published

        // every block: identical argmax (first-max == jnp.argmax tie-break)
        if (tid < NFRM) s_g[tid] = g_gains[it][tid];
        __syncthreads();
        if (tid == 0) {
            int bg = -2, bs = 0;
            for (int s = 0; s < NFRM; s++) {
                int g = (selbits[s >> 5] >> (s & 31)) & 1 ? -1 : s_g[s];
                if (g > bg) { bg = g; bs = s; }
            }
            selbits[bs >> 5] |= 1u << (bs & 31);
            s_best = bs;
            if (f == 0) {                       // record outputs
                out[it] = (float)bs;
                out[KSEL + it] = (float)bg;
            }
        }
        __syncthreads();
        const unsigned* row = g_occ[s_best];
        // each thread updates exactly the cov[] words it reads in the gain loop -> no sync needed
        for (int w = tid; w < VW; w += NT) cov[w] |= row[w];
        __syncthreads();
    }

    // ================= finalize: total coverage =================
    if (f == 0) {
        int acc = 0;
        for (int w = tid; w < VW; w += NT) acc += __popc(cov[w]);
        #pragma unroll
        for (int o = 16; o; o >>= 1) acc += __shfl_down_sync(0xFFFFFFFFu, acc, o);
        if ((tid & 31) == 0) s_redi[tid >> 5] = acc;
        __syncthreads();
        if (tid == 0) {
            int tot = 0;
            for (int w = 0; w < NW; w++) tot += s_redi[w];
            if (2 * KSEL < out_size) out[2 * KSEL] = (float)tot;
        }
        // defensive: zero any tail beyond 33 elements (output is poisoned to 0xAA)
        for (int w = 2 * KSEL + 1 + tid; w < out_size; w += NT) out[w] = 0.0f;
    }
}

// ---------------- launch: ONE graph node ----------------
extern "C" void kernel_launch(void* const* d_in, const int* in_sizes, int n_in,
                              void* d_out, int out_size) {
    // metadata order: depth, depth_conf, world_points, world_points_conf, pose_enc
    const float* wp   = (const float*)d_in[2];
    const float* conf = (const float*)d_in[3];
    float* out = (float*)d_out;
    k_fused<<<NFRM, NT>>>(wp, conf, out, out_size);
}